// round 15
// baseline (speedup 1.0000x reference)
#include <cuda_runtime.h>
#include <cuda_fp16.h>

#define D 128
#define NMAX 100000
#define PAD 20

__device__ __half g_h[2][(size_t)NMAX * D];
__device__ int g_idx64;

__device__ __forceinline__ unsigned f2tf32(float f) {
    unsigned u;
    asm("cvt.rna.tf32.f32 %0, %1;" : "=r"(u) : "f"(f));
    return u;
}

__device__ __forceinline__ void mma_tf32(float c[4], unsigned a0, unsigned a1,
                                         unsigned a2, unsigned a3,
                                         unsigned b0, unsigned b1) {
    asm volatile(
        "mma.sync.aligned.m16n8k8.row.col.f32.tf32.tf32.f32 "
        "{%0,%1,%2,%3},{%4,%5,%6,%7},{%8,%9},{%0,%1,%2,%3};"
        : "+f"(c[0]), "+f"(c[1]), "+f"(c[2]), "+f"(c[3])
        : "r"(a0), "r"(a1), "r"(a2), "r"(a3), "r"(b0), "r"(b1));
}

// 128-bit evict_last gather via cache_hint policy.
__device__ __forceinline__ uint4 ldg128_el(const void* p, unsigned long long pol) {
    uint4 r;
    asm volatile("ld.global.nc.L2::cache_hint.v4.u32 {%0,%1,%2,%3}, [%4], %5;"
                 : "=r"(r.x), "=r"(r.y), "=r"(r.z), "=r"(r.w)
                 : "l"(p), "l"(pol));
    return r;
}

__device__ __forceinline__ void stg_ef(void* p, float4 v, unsigned long long pol) {
    asm volatile("st.global.L2::cache_hint.v4.f32 [%0], {%1,%2,%3,%4}, %5;"
                 :: "l"(p), "f"(v.x), "f"(v.y), "f"(v.z), "f"(v.w), "l"(pol)
                 : "memory");
}

// ---------------------------------------------------------------------------
// Node GEMM (measured-best, unchanged): tf32 mma, one half per blockIdx.y,
// 256 threads, register-pipelined K loop, 2 blocks/SM.
// ---------------------------------------------------------------------------
__global__ __launch_bounds__(256, 2) void node_gemm_half(
    const float* __restrict__ x,
    const float* __restrict__ Wsrc, const float* __restrict__ bsrc,
    const float* __restrict__ Wdst, const float* __restrict__ bdst,
    const long long* __restrict__ idxprobe, int N)
{
    __shared__ unsigned As[128][PAD];
    __shared__ unsigned Bs[128][PAD];

    const int tid  = threadIdx.x;
    const int half = blockIdx.y;

    if (blockIdx.x == 0 && half == 0 && tid == 0) {
        int ok = 0;
#pragma unroll
        for (int i = 0; i < 16; i++) {
            long long v = idxprobe[i];
            if (v >= 0 && v < (long long)N) ok++;
        }
        g_idx64 = (ok >= 12) ? 1 : 0;
    }

    const float* __restrict__ W  = half ? Wdst : Wsrc;
    const float* __restrict__ bh = half ? bdst : bsrc;
    __half* __restrict__ out = g_h[half];

    const int wid  = tid >> 5;
    const int lane = tid & 31;
    const int wm   = (wid >> 2) * 64;
    const int wn   = (wid & 3) * 32;
    const int row0 = blockIdx.x * 128;
    const int tg   = lane >> 2;
    const int tr   = lane & 3;

    float acc[4][4][4];
#pragma unroll
    for (int i = 0; i < 4; i++)
#pragma unroll
        for (int j = 0; j < 4; j++)
#pragma unroll
            for (int k = 0; k < 4; k++) acc[i][j][k] = 0.0f;

    const int lrow = tid >> 1;
    const int lcol = (tid & 1) * 8;
    const bool rowok = (row0 + lrow < N);
    const float* xrow = x + (size_t)(row0 + lrow) * D + lcol;
    const float* wr   = W + (size_t)lrow * D + lcol;

    float4 a0v = make_float4(0.f,0.f,0.f,0.f), a1v = a0v;
    if (rowok) { a0v = *(const float4*)xrow; a1v = *(const float4*)(xrow + 4); }
    float4 w0v = *(const float4*)wr;
    float4 w1v = *(const float4*)(wr + 4);

#pragma unroll
    for (int it = 0; it < 8; it++) {
        As[lrow][lcol+0] = f2tf32(a0v.x); As[lrow][lcol+1] = f2tf32(a0v.y);
        As[lrow][lcol+2] = f2tf32(a0v.z); As[lrow][lcol+3] = f2tf32(a0v.w);
        As[lrow][lcol+4] = f2tf32(a1v.x); As[lrow][lcol+5] = f2tf32(a1v.y);
        As[lrow][lcol+6] = f2tf32(a1v.z); As[lrow][lcol+7] = f2tf32(a1v.w);
        Bs[lrow][lcol+0] = f2tf32(w0v.x); Bs[lrow][lcol+1] = f2tf32(w0v.y);
        Bs[lrow][lcol+2] = f2tf32(w0v.z); Bs[lrow][lcol+3] = f2tf32(w0v.w);
        Bs[lrow][lcol+4] = f2tf32(w1v.x); Bs[lrow][lcol+5] = f2tf32(w1v.y);
        Bs[lrow][lcol+6] = f2tf32(w1v.z); Bs[lrow][lcol+7] = f2tf32(w1v.w);
        __syncthreads();

        if (it < 7) {
            const int off = (it + 1) * 16;
            a0v = make_float4(0.f,0.f,0.f,0.f); a1v = a0v;
            if (rowok) {
                a0v = *(const float4*)(xrow + off);
                a1v = *(const float4*)(xrow + off + 4);
            }
            w0v = *(const float4*)(wr + off);
            w1v = *(const float4*)(wr + off + 4);
        }

#pragma unroll
        for (int kk = 0; kk < 16; kk += 8) {
            unsigned bf[4][2];
#pragma unroll
            for (int nt = 0; nt < 4; nt++) {
                bf[nt][0] = Bs[wn + nt*8 + tg][kk + tr];
                bf[nt][1] = Bs[wn + nt*8 + tg][kk + tr + 4];
            }
#pragma unroll
            for (int mt = 0; mt < 4; mt++) {
                const int ar = wm + mt*16 + tg;
                unsigned q0 = As[ar    ][kk + tr];
                unsigned q1 = As[ar + 8][kk + tr];
                unsigned q2 = As[ar    ][kk + tr + 4];
                unsigned q3 = As[ar + 8][kk + tr + 4];
#pragma unroll
                for (int nt = 0; nt < 4; nt++)
                    mma_tf32(acc[mt][nt], q0, q1, q2, q3, bf[nt][0], bf[nt][1]);
            }
        }
        __syncthreads();
    }

#pragma unroll
    for (int mt = 0; mt < 4; mt++) {
#pragma unroll
        for (int nt = 0; nt < 4; nt++) {
            const int cg = wn + nt*8 + 2*tr;
            const float bb0 = bh[cg], bb1 = bh[cg + 1];
            const int r0g = row0 + wm + mt*16 + tg;
            const int r1g = r0g + 8;
            if (r0g < N) {
                __half2 h = __floats2half2_rn(acc[mt][nt][0] + bb0,
                                              acc[mt][nt][1] + bb1);
                *(__half2*)(out + (size_t)r0g * D + cg) = h;
            }
            if (r1g < N) {
                __half2 h = __floats2half2_rn(acc[mt][nt][2] + bb0,
                                              acc[mt][nt][3] + bb1);
                *(__half2*)(out + (size_t)r1g * D + cg) = h;
            }
        }
    }
}

// ---------------------------------------------------------------------------
// Edge pass: grid-stride one-wave persistent, 16 lanes/edge, lane sl owns
// cols [sl*8, sl*8+8). One LDG.128 per h array per lane (half the gather
// instructions of the uint2 version); stores are 32B contiguous per lane.
// Index prefetch one iteration ahead; no __syncthreads.
// ---------------------------------------------------------------------------
__global__ __launch_bounds__(256, 7) void edge_kernel(
    const void* __restrict__ srcp, const void* __restrict__ dstp,
    const float* __restrict__ W_out, const float* __restrict__ b_out,
    float* __restrict__ score, float* __restrict__ embs,
    long long E, int N)
{
    const int tid  = threadIdx.x;
    const int warp = tid >> 5;
    const int lane = tid & 31;
    const int sub  = lane >> 4;
    const int sl   = lane & 15;

    unsigned long long pol_l, pol_s;
    asm("createpolicy.fractional.L2::evict_last.b64 %0, 1.0;"  : "=l"(pol_l));
    asm("createpolicy.fractional.L2::evict_first.b64 %0, 1.0;" : "=l"(pol_s));

    // W_out fragments for cols sl*8 .. sl*8+7 (row-5-verified indexing).
    const float4* W4 = (const float4*)W_out;
    const float4 wa0 = __ldg(W4 + 2 * sl);
    const float4 wa1 = __ldg(W4 + 2 * sl + 1);
    const float4 wb0 = __ldg(W4 + 32 + 2 * sl);
    const float4 wb1 = __ldg(W4 + 32 + 2 * sl + 1);
    const float  bo0 = __ldg(b_out);
    const float  bo1 = __ldg(b_out + 1);

    const __half* __restrict__ hs = g_h[0];
    const __half* __restrict__ hd = g_h[1];
    const bool i64 = (g_idx64 != 0);

    const long long stride = (long long)gridDim.x * 16;
    long long e = (long long)blockIdx.x * 16 + warp * 2 + sub;

    int s_n = 0, d_n = 0;
    if (e < E) {
        if (i64) {
            s_n = (int)((const long long*)srcp)[e];
            d_n = (int)((const long long*)dstp)[e];
        } else {
            s_n = ((const int*)srcp)[e];
            d_n = ((const int*)dstp)[e];
        }
    }

    const __half2 z = __float2half2_rn(0.0f);

    while (e < E) {
        const int s = min(max(s_n, 0), N - 1);
        const int d = min(max(d_n, 0), N - 1);
        const long long en = e + stride;

        // One 16B gather per array per lane: cols [sl*8, sl*8+8).
        const uint4 pa = ldg128_el((const uint4*)(hs + (size_t)s * D) + sl, pol_l);
        const uint4 pb = ldg128_el((const uint4*)(hd + (size_t)d * D) + sl, pol_l);

        // Prefetch next iteration's indices while gathers are in flight.
        if (en < E) {
            if (i64) {
                s_n = (int)((const long long*)srcp)[en];
                d_n = (int)((const long long*)dstp)[en];
            } else {
                s_n = ((const int*)srcp)[en];
                d_n = ((const int*)dstp)[en];
            }
        }

        __half2 v0 = __hmax2(__hadd2(*(const __half2*)&pa.x, *(const __half2*)&pb.x), z);
        __half2 v1 = __hmax2(__hadd2(*(const __half2*)&pa.y, *(const __half2*)&pb.y), z);
        __half2 v2 = __hmax2(__hadd2(*(const __half2*)&pa.z, *(const __half2*)&pb.z), z);
        __half2 v3 = __hmax2(__hadd2(*(const __half2*)&pa.w, *(const __half2*)&pb.w), z);

        float2 f0 = __half22float2(v0);
        float2 f1 = __half22float2(v1);
        float2 f2 = __half22float2(v2);
        float2 f3 = __half22float2(v3);

        float* ep = embs + (size_t)e * D + sl * 8;
        stg_ef(ep,     make_float4(f0.x, f0.y, f1.x, f1.y), pol_s);
        stg_ef(ep + 4, make_float4(f2.x, f2.y, f3.x, f3.y), pol_s);

        float d0 = f0.x*wa0.x + f0.y*wa0.y + f1.x*wa0.z + f1.y*wa0.w
                 + f2.x*wa1.x + f2.y*wa1.y + f3.x*wa1.z + f3.y*wa1.w;
        float d1 = f0.x*wb0.x + f0.y*wb0.y + f1.x*wb0.z + f1.y*wb0.w
                 + f2.x*wb1.x + f2.y*wb1.y + f3.x*wb1.z + f3.y*wb1.w;

#pragma unroll
        for (int o = 8; o > 0; o >>= 1) {
            d0 += __shfl_xor_sync(0xffffffffu, d0, o);
            d1 += __shfl_xor_sync(0xffffffffu, d1, o);
        }
        if (sl == 0)
            ((float2*)score)[e] = make_float2(d0 + bo0, d1 + bo1);

        e = en;
    }
}

extern "C" void kernel_launch(void* const* d_in, const int* in_sizes, int n_in,
                              void* d_out, int out_size)
{
    const float* x     = (const float*)d_in[0];
    const void*  src   = d_in[1];
    const void*  dst   = d_in[2];
    const float* W_src = (const float*)d_in[3];
    const float* b_src = (const float*)d_in[4];
    const float* W_dst = (const float*)d_in[5];
    const float* b_dst = (const float*)d_in[6];
    const float* W_out = (const float*)d_in[7];
    const float* b_out = (const float*)d_in[8];

    const int N = in_sizes[0] / D;
    const long long E = in_sizes[1];

    float* out   = (float*)d_out;
    float* score = out;                       // [E, 2]
    float* embs  = out + (size_t)E * 2;       // [E, 128]

    dim3 gg((N + 127) / 128, 2);
    node_gemm_half<<<gg, 256>>>(x, W_src, b_src, W_dst, b_dst,
                                (const long long*)src, N);

    // Exactly one resident wave: 7 blocks/SM x 148 SMs (36-reg cap).
    const int eb = 148 * 7;
    edge_kernel<<<eb, 256>>>(src, dst, W_out, b_out, score, embs, E, N);
}

// round 16
// speedup vs baseline: 1.4089x; 1.4089x over previous
#include <cuda_runtime.h>
#include <cuda_fp16.h>

#define D 128
#define NMAX 100000
#define PAD 20

__device__ __half g_h[2][(size_t)NMAX * D];
__device__ int g_idx64;

__device__ __forceinline__ unsigned f2tf32(float f) {
    unsigned u;
    asm("cvt.rna.tf32.f32 %0, %1;" : "=r"(u) : "f"(f));
    return u;
}

__device__ __forceinline__ void mma_tf32(float c[4], unsigned a0, unsigned a1,
                                         unsigned a2, unsigned a3,
                                         unsigned b0, unsigned b1) {
    asm volatile(
        "mma.sync.aligned.m16n8k8.row.col.f32.tf32.tf32.f32 "
        "{%0,%1,%2,%3},{%4,%5,%6,%7},{%8,%9},{%0,%1,%2,%3};"
        : "+f"(c[0]), "+f"(c[1]), "+f"(c[2]), "+f"(c[3])
        : "r"(a0), "r"(a1), "r"(a2), "r"(a3), "r"(b0), "r"(b1));
}

__device__ __forceinline__ uint2 ldg_el(const void* p, unsigned long long pol) {
    uint2 r;
    asm volatile("ld.global.nc.L2::cache_hint.v2.u32 {%0,%1}, [%2], %3;"
                 : "=r"(r.x), "=r"(r.y) : "l"(p), "l"(pol));
    return r;
}

__device__ __forceinline__ void stg_ef(void* p, float4 v, unsigned long long pol) {
    asm volatile("st.global.L2::cache_hint.v4.f32 [%0], {%1,%2,%3,%4}, %5;"
                 :: "l"(p), "f"(v.x), "f"(v.y), "f"(v.z), "f"(v.w), "l"(pol)
                 : "memory");
}

// ---------------------------------------------------------------------------
// Node GEMM: tf32 mma, one half per blockIdx.y, 256 threads, DOUBLE-BUFFERED
// smem (compute buf p while storing buf p^1): 9 syncs instead of 16.
// ---------------------------------------------------------------------------
__global__ __launch_bounds__(256, 2) void node_gemm_half(
    const float* __restrict__ x,
    const float* __restrict__ Wsrc, const float* __restrict__ bsrc,
    const float* __restrict__ Wdst, const float* __restrict__ bdst,
    const long long* __restrict__ idxprobe, int N)
{
    __shared__ unsigned As[2][128][PAD];
    __shared__ unsigned Bs[2][128][PAD];

    const int tid  = threadIdx.x;
    const int half = blockIdx.y;

    if (blockIdx.x == 0 && half == 0 && tid == 0) {
        int ok = 0;
#pragma unroll
        for (int i = 0; i < 16; i++) {
            long long v = idxprobe[i];
            if (v >= 0 && v < (long long)N) ok++;
        }
        g_idx64 = (ok >= 12) ? 1 : 0;
    }

    const float* __restrict__ W  = half ? Wdst : Wsrc;
    const float* __restrict__ bh = half ? bdst : bsrc;
    __half* __restrict__ out = g_h[half];

    const int wid  = tid >> 5;
    const int lane = tid & 31;
    const int wm   = (wid >> 2) * 64;
    const int wn   = (wid & 3) * 32;
    const int row0 = blockIdx.x * 128;
    const int tg   = lane >> 2;
    const int tr   = lane & 3;

    float acc[4][4][4];
#pragma unroll
    for (int i = 0; i < 4; i++)
#pragma unroll
        for (int j = 0; j < 4; j++)
#pragma unroll
            for (int k = 0; k < 4; k++) acc[i][j][k] = 0.0f;

    const int lrow = tid >> 1;
    const int lcol = (tid & 1) * 8;
    const bool rowok = (row0 + lrow < N);
    const float* xrow = x + (size_t)(row0 + lrow) * D + lcol;
    const float* wr   = W + (size_t)lrow * D + lcol;

    // Prologue: tile 0 -> regs -> buf 0.
    float4 a0v = make_float4(0.f,0.f,0.f,0.f), a1v = a0v;
    if (rowok) { a0v = *(const float4*)xrow; a1v = *(const float4*)(xrow + 4); }
    float4 w0v = *(const float4*)wr;
    float4 w1v = *(const float4*)(wr + 4);

    As[0][lrow][lcol+0] = f2tf32(a0v.x); As[0][lrow][lcol+1] = f2tf32(a0v.y);
    As[0][lrow][lcol+2] = f2tf32(a0v.z); As[0][lrow][lcol+3] = f2tf32(a0v.w);
    As[0][lrow][lcol+4] = f2tf32(a1v.x); As[0][lrow][lcol+5] = f2tf32(a1v.y);
    As[0][lrow][lcol+6] = f2tf32(a1v.z); As[0][lrow][lcol+7] = f2tf32(a1v.w);
    Bs[0][lrow][lcol+0] = f2tf32(w0v.x); Bs[0][lrow][lcol+1] = f2tf32(w0v.y);
    Bs[0][lrow][lcol+2] = f2tf32(w0v.z); Bs[0][lrow][lcol+3] = f2tf32(w0v.w);
    Bs[0][lrow][lcol+4] = f2tf32(w1v.x); Bs[0][lrow][lcol+5] = f2tf32(w1v.y);
    Bs[0][lrow][lcol+6] = f2tf32(w1v.z); Bs[0][lrow][lcol+7] = f2tf32(w1v.w);
    __syncthreads();

    int p = 0;
#pragma unroll
    for (int it = 0; it < 8; it++) {
        // Issue next tile's global loads (latency hidden behind compute).
        if (it < 7) {
            const int off = (it + 1) * 16;
            a0v = make_float4(0.f,0.f,0.f,0.f); a1v = a0v;
            if (rowok) {
                a0v = *(const float4*)(xrow + off);
                a1v = *(const float4*)(xrow + off + 4);
            }
            w0v = *(const float4*)(wr + off);
            w1v = *(const float4*)(wr + off + 4);
        }

        // Compute from buffer p.
#pragma unroll
        for (int kk = 0; kk < 16; kk += 8) {
            unsigned bf[4][2];
#pragma unroll
            for (int nt = 0; nt < 4; nt++) {
                bf[nt][0] = Bs[p][wn + nt*8 + tg][kk + tr];
                bf[nt][1] = Bs[p][wn + nt*8 + tg][kk + tr + 4];
            }
#pragma unroll
            for (int mt = 0; mt < 4; mt++) {
                const int ar = wm + mt*16 + tg;
                unsigned q0 = As[p][ar    ][kk + tr];
                unsigned q1 = As[p][ar + 8][kk + tr];
                unsigned q2 = As[p][ar    ][kk + tr + 4];
                unsigned q3 = As[p][ar + 8][kk + tr + 4];
#pragma unroll
                for (int nt = 0; nt < 4; nt++)
                    mma_tf32(acc[mt][nt], q0, q1, q2, q3, bf[nt][0], bf[nt][1]);
            }
        }

        // Store next tile into the other buffer; one sync per iteration.
        if (it < 7) {
            const int q = p ^ 1;
            As[q][lrow][lcol+0] = f2tf32(a0v.x); As[q][lrow][lcol+1] = f2tf32(a0v.y);
            As[q][lrow][lcol+2] = f2tf32(a0v.z); As[q][lrow][lcol+3] = f2tf32(a0v.w);
            As[q][lrow][lcol+4] = f2tf32(a1v.x); As[q][lrow][lcol+5] = f2tf32(a1v.y);
            As[q][lrow][lcol+6] = f2tf32(a1v.z); As[q][lrow][lcol+7] = f2tf32(a1v.w);
            Bs[q][lrow][lcol+0] = f2tf32(w0v.x); Bs[q][lrow][lcol+1] = f2tf32(w0v.y);
            Bs[q][lrow][lcol+2] = f2tf32(w0v.z); Bs[q][lrow][lcol+3] = f2tf32(w0v.w);
            Bs[q][lrow][lcol+4] = f2tf32(w1v.x); Bs[q][lrow][lcol+5] = f2tf32(w1v.y);
            Bs[q][lrow][lcol+6] = f2tf32(w1v.z); Bs[q][lrow][lcol+7] = f2tf32(w1v.w);
            __syncthreads();
            p = q;
        }
    }

#pragma unroll
    for (int mt = 0; mt < 4; mt++) {
#pragma unroll
        for (int nt = 0; nt < 4; nt++) {
            const int cg = wn + nt*8 + 2*tr;
            const float bb0 = bh[cg], bb1 = bh[cg + 1];
            const int r0g = row0 + wm + mt*16 + tg;
            const int r1g = r0g + 8;
            if (r0g < N) {
                __half2 h = __floats2half2_rn(acc[mt][nt][0] + bb0,
                                              acc[mt][nt][1] + bb1);
                *(__half2*)(out + (size_t)r0g * D + cg) = h;
            }
            if (r1g < N) {
                __half2 h = __floats2half2_rn(acc[mt][nt][2] + bb0,
                                              acc[mt][nt][3] + bb1);
                *(__half2*)(out + (size_t)r1g * D + cg) = h;
            }
        }
    }
}

// ---------------------------------------------------------------------------
// Edge pass (round-14 measured best, byte-for-byte): grid-stride one-wave,
// 16 lanes/edge, uint2 gathers, index prefetch, launch_bounds(256,6).
// ---------------------------------------------------------------------------
__global__ __launch_bounds__(256, 6) void edge_kernel(
    const void* __restrict__ srcp, const void* __restrict__ dstp,
    const float* __restrict__ W_out, const float* __restrict__ b_out,
    float* __restrict__ score, float* __restrict__ embs,
    long long E, int N)
{
    const int tid  = threadIdx.x;
    const int warp = tid >> 5;
    const int lane = tid & 31;
    const int sub  = lane >> 4;
    const int sl   = lane & 15;

    unsigned long long pol_l, pol_s;
    asm("createpolicy.fractional.L2::evict_last.b64 %0, 1.0;"  : "=l"(pol_l));
    asm("createpolicy.fractional.L2::evict_first.b64 %0, 1.0;" : "=l"(pol_s));

    const float4* W4 = (const float4*)W_out;
    const float4 wa_lo = __ldg(W4 + sl);
    const float4 wa_hi = __ldg(W4 + 16 + sl);
    const float4 wb_lo = __ldg(W4 + 32 + sl);
    const float4 wb_hi = __ldg(W4 + 48 + sl);
    const float  bo0   = __ldg(b_out);
    const float  bo1   = __ldg(b_out + 1);

    const __half* __restrict__ hs = g_h[0];
    const __half* __restrict__ hd = g_h[1];
    const bool i64 = (g_idx64 != 0);

    const long long stride = (long long)gridDim.x * 16;
    long long e = (long long)blockIdx.x * 16 + warp * 2 + sub;

    int s_n = 0, d_n = 0;
    if (e < E) {
        if (i64) {
            s_n = (int)((const long long*)srcp)[e];
            d_n = (int)((const long long*)dstp)[e];
        } else {
            s_n = ((const int*)srcp)[e];
            d_n = ((const int*)dstp)[e];
        }
    }

    const __half2 z = __float2half2_rn(0.0f);

    while (e < E) {
        const int s = min(max(s_n, 0), N - 1);
        const int d = min(max(d_n, 0), N - 1);
        const long long en = e + stride;

        const __half* rs = hs + (size_t)s * D;
        const __half* rd = hd + (size_t)d * D;
        const uint2 sa_lo = ldg_el((const uint2*)rs + sl, pol_l);
        const uint2 sa_hi = ldg_el((const uint2*)(rs + 64) + sl, pol_l);
        const uint2 da_lo = ldg_el((const uint2*)rd + sl, pol_l);
        const uint2 da_hi = ldg_el((const uint2*)(rd + 64) + sl, pol_l);

        if (en < E) {
            if (i64) {
                s_n = (int)((const long long*)srcp)[en];
                d_n = (int)((const long long*)dstp)[en];
            } else {
                s_n = ((const int*)srcp)[en];
                d_n = ((const int*)dstp)[en];
            }
        }

        __half2 l0 = __hmax2(__hadd2(*(const __half2*)&sa_lo.x, *(const __half2*)&da_lo.x), z);
        __half2 l1 = __hmax2(__hadd2(*(const __half2*)&sa_lo.y, *(const __half2*)&da_lo.y), z);
        __half2 h0 = __hmax2(__hadd2(*(const __half2*)&sa_hi.x, *(const __half2*)&da_hi.x), z);
        __half2 h1 = __hmax2(__hadd2(*(const __half2*)&sa_hi.y, *(const __half2*)&da_hi.y), z);

        float2 fl0 = __half22float2(l0);
        float2 fl1 = __half22float2(l1);
        float2 fh0 = __half22float2(h0);
        float2 fh1 = __half22float2(h1);

        float* ep = embs + (size_t)e * D;
        stg_ef(ep + sl * 4,      make_float4(fl0.x, fl0.y, fl1.x, fl1.y), pol_s);
        stg_ef(ep + 64 + sl * 4, make_float4(fh0.x, fh0.y, fh1.x, fh1.y), pol_s);

        float d0 = fl0.x*wa_lo.x + fl0.y*wa_lo.y + fl1.x*wa_lo.z + fl1.y*wa_lo.w
                 + fh0.x*wa_hi.x + fh0.y*wa_hi.y + fh1.x*wa_hi.z + fh1.y*wa_hi.w;
        float d1 = fl0.x*wb_lo.x + fl0.y*wb_lo.y + fl1.x*wb_lo.z + fl1.y*wb_lo.w
                 + fh0.x*wb_hi.x + fh0.y*wb_hi.y + fh1.x*wb_hi.z + fh1.y*wb_hi.w;

#pragma unroll
        for (int o = 8; o > 0; o >>= 1) {
            d0 += __shfl_xor_sync(0xffffffffu, d0, o);
            d1 += __shfl_xor_sync(0xffffffffu, d1, o);
        }
        if (sl == 0)
            ((float2*)score)[e] = make_float2(d0 + bo0, d1 + bo1);

        e = en;
    }
}

extern "C" void kernel_launch(void* const* d_in, const int* in_sizes, int n_in,
                              void* d_out, int out_size)
{
    const float* x     = (const float*)d_in[0];
    const void*  src   = d_in[1];
    const void*  dst   = d_in[2];
    const float* W_src = (const float*)d_in[3];
    const float* b_src = (const float*)d_in[4];
    const float* W_dst = (const float*)d_in[5];
    const float* b_dst = (const float*)d_in[6];
    const float* W_out = (const float*)d_in[7];
    const float* b_out = (const float*)d_in[8];

    const int N = in_sizes[0] / D;
    const long long E = in_sizes[1];

    float* out   = (float*)d_out;
    float* score = out;                       // [E, 2]
    float* embs  = out + (size_t)E * 2;       // [E, 128]

    dim3 gg((N + 127) / 128, 2);
    node_gemm_half<<<gg, 256>>>(x, W_src, b_src, W_dst, b_dst,
                                (const long long*)src, N);

    // Exactly one resident wave: 6 blocks/SM x 148 SMs.
    const int eb = 148 * 6;
    edge_kernel<<<eb, 256>>>(src, dst, W_out, b_out, score, embs, E, N);
}